// round 1
// baseline (speedup 1.0000x reference)
#include <cuda_runtime.h>
#include <math.h>

#define N_ATOMS 1500
#define NODE_DIM 128
#define HIDDEN 64
#define SPH_DIM 480
#define OFF0 128
#define MUL1E 64
#define HID1E 32
#define NUM_BASIS 20
#define CUTOFF 5.0f

#define TB 512
#define TA 4

// node n: [coord.xyz, ni.xyz, nj.xyz] as 3x float4
__device__ float4 g_node[N_ATOMS * 3];

__device__ __forceinline__ float sigmoidf_(float x) {
    return 1.0f / (1.0f + __expf(-x));
}

// ---------------------------------------------------------------------------
// Stage 1: per-node MLPs. 1 block per node, 384 threads:
//   [0,64)    scalar MLP set i   (one hidden col per thread)
//   [64,128)  scalar MLP set j
//   [128,224) spherical set i    (96 threads = 32 hidden x 3 dims)
//   [224,320) spherical set j
// ---------------------------------------------------------------------------
__global__ __launch_bounds__(384) void node_kernel(
    const float* __restrict__ xs_g, const float* __restrict__ xsph,
    const float* __restrict__ coord,
    const float* __restrict__ Wsi1, const float* __restrict__ Wsi2,
    const float* __restrict__ Wsj1, const float* __restrict__ Wsj2,
    const float* __restrict__ Wpi1, const float* __restrict__ Wpi2,
    const float* __restrict__ Wpj1, const float* __restrict__ Wpj2)
{
    int n = blockIdx.x;
    int tid = threadIdx.x;

    __shared__ float xs[NODE_DIM];
    __shared__ float sp[2 * HIDDEN];
    __shared__ float h1e[2][HID1E][3];
    __shared__ float hg[2][HID1E][3];
    __shared__ float outp[2][3];
    __shared__ float sred[2];

    for (int k = tid; k < NODE_DIM; k += 384) xs[k] = xs_g[n * NODE_DIM + k];
    __syncthreads();

    if (tid < 2 * HIDDEN) {
        int set = tid >> 6;
        int col = tid & 63;
        const float* W1 = set ? Wsj1 : Wsi1;
        const float* W2 = set ? Wsj2 : Wsi2;
        float acc = 0.f;
        #pragma unroll 8
        for (int k = 0; k < NODE_DIM; k++)
            acc = fmaf(xs[k], __ldg(&W1[k * HIDDEN + col]), acc);
        float s = acc * sigmoidf_(acc);          // silu
        sp[tid] = s * __ldg(&W2[col]);
    } else if (tid < 320) {
        int t = tid - 128;
        int set = t / 96;
        int idx = t % 96;
        int hc = idx / 3, dd = idx - hc * 3;
        const float* W1 = set ? Wpj1 : Wpi1;
        const float* v = xsph + (size_t)n * SPH_DIM + OFF0 + dd;
        float acc = 0.f;
        #pragma unroll 8
        for (int m = 0; m < MUL1E; m++)
            acc = fmaf(__ldg(&v[m * 3]), __ldg(&W1[m * HID1E + hc]), acc);
        h1e[set][hc][dd] = acc * 0.125f;         // 1/sqrt(64)
    }
    __syncthreads();

    if (tid >= 128 && tid < 320) {
        int t = tid - 128;
        int set = t / 96;
        int idx = t % 96;
        int hc = idx / 3, dd = idx - hc * 3;
        const float* W2 = set ? Wpj2 : Wpi2;
        float h0 = h1e[set][hc][0], h1 = h1e[set][hc][1], h2 = h1e[set][hc][2];
        float nrm = sqrtf(h0 * h0 + h1 * h1 + h2 * h2);
        float gate = sigmoidf_(nrm);
        hg[set][hc][dd] = h1e[set][hc][dd] * gate * __ldg(&W2[hc]);
    }
    if (tid < 2) {
        float s = 0.f;
        for (int k = 0; k < HIDDEN; k++) s += sp[tid * HIDDEN + k];
        sred[tid] = s;
    }
    __syncthreads();

    if (tid < 6) {
        int set = tid / 3, dd = tid % 3;
        float s = 0.f;
        for (int h = 0; h < HID1E; h++) s += hg[set][h][dd];
        outp[set][dd] = s * 0.17677669529663687f;   // 1/sqrt(32)
    }
    __syncthreads();

    if (tid == 0) {
        float fi = 1.f + sred[0];
        float fj = 1.f + sred[1];
        // e3nn 1e (y,z,x) -> (x,y,z): out[:, [2,0,1]]
        float nix = outp[0][2] * fi, niy = outp[0][0] * fi, niz = outp[0][1] * fi;
        float njx = outp[1][2] * fj, njy = outp[1][0] * fj, njz = outp[1][1] * fj;
        g_node[n * 3 + 0] = make_float4(coord[n * 3 + 0], coord[n * 3 + 1], coord[n * 3 + 2], 0.f);
        g_node[n * 3 + 1] = make_float4(nix, niy, niz, 0.f);
        g_node[n * 3 + 2] = make_float4(njx, njy, njz, 0.f);
    }
}

// ---------------------------------------------------------------------------
// Stage 2: edges. Block = 512 b-values x TA=4 a-values.
// out[a*N+b][r][c] = 0.5 * fc(d_ab) * (ni_a[r]*nj_b[c] + nj_a[r]*ni_b[c])
// Staged through smem for fully coalesced stores.
// ---------------------------------------------------------------------------
__global__ __launch_bounds__(TB, 2) void edge_kernel(
    const float* __restrict__ Wrbf, float* __restrict__ out)
{
    __shared__ float stage[TB * 9];
    int tid = threadIdx.x;
    int b0 = blockIdx.x * TB;
    int b = b0 + tid;
    bool valid = b < N_ATOMS;

    float4 cb, nib, njb;
    if (valid) {
        cb  = g_node[b * 3 + 0];
        nib = g_node[b * 3 + 1];
        njb = g_node[b * 3 + 2];
    }

    float w[NUM_BASIS];
    #pragma unroll
    for (int k = 0; k < NUM_BASIS; k++) w[k] = __ldg(&Wrbf[k]);

    const int nb = min(TB, N_ATOMS - b0);
    const float dO = CUTOFF / (float)(NUM_BASIS - 1);
    const float coeff = -0.5f / (dO * dO);
    const float c2e = coeff * 1.4426950408889634f;   // exp -> exp2 domain

    #pragma unroll
    for (int ai = 0; ai < TA; ai++) {
        int a = blockIdx.y * TA + ai;
        float4 ca  = g_node[a * 3 + 0];
        float4 nia = g_node[a * 3 + 1];
        float4 nja = g_node[a * 3 + 2];

        if (valid) {
            float dx = ca.x - cb.x, dy = ca.y - cb.y, dz = ca.z - cb.z;
            float d2 = fmaf(dx, dx, fmaf(dy, dy, dz * dz));
            float d;
            asm("sqrt.approx.f32 %0, %1;" : "=f"(d) : "f"(d2));  // sqrt(0)=0 ok

            float fc = 0.f;
            #pragma unroll
            for (int k = 0; k < NUM_BASIS; k++) {
                float t = d - (float)k * dO;
                float arg = (c2e * t) * t;
                float e;
                asm("ex2.approx.f32 %0, %1;" : "=f"(e) : "f"(arg));
                fc = fmaf(w[k], e, fc);
            }
            float f = 0.5f * fc;

            float* st = &stage[tid * 9];
            st[0] = f * (nia.x * njb.x + nja.x * nib.x);
            st[1] = f * (nia.x * njb.y + nja.x * nib.y);
            st[2] = f * (nia.x * njb.z + nja.x * nib.z);
            st[3] = f * (nia.y * njb.x + nja.y * nib.x);
            st[4] = f * (nia.y * njb.y + nja.y * nib.y);
            st[5] = f * (nia.y * njb.z + nja.y * nib.z);
            st[6] = f * (nia.z * njb.x + nja.z * nib.x);
            st[7] = f * (nia.z * njb.y + nja.z * nib.y);
            st[8] = f * (nia.z * njb.z + nja.z * nib.z);
        }
        __syncthreads();

        float* dst = out + ((size_t)a * N_ATOMS + b0) * 9;
        int tot = nb * 9;
        for (int idx = tid; idx < tot; idx += TB) dst[idx] = stage[idx];
        __syncthreads();
    }
}

extern "C" void kernel_launch(void* const* d_in, const int* in_sizes, int n_in,
                              void* d_out, int out_size)
{
    const float* xs    = (const float*)d_in[0];
    const float* xsph  = (const float*)d_in[1];
    const float* coord = (const float*)d_in[2];
    // d_in[3] = fc_edge_index (int32, full graph i-major; structure known, unused)
    const float* Wsi1 = (const float*)d_in[4];
    const float* Wsi2 = (const float*)d_in[5];
    const float* Wsj1 = (const float*)d_in[6];
    const float* Wsj2 = (const float*)d_in[7];
    const float* Wpi1 = (const float*)d_in[8];
    const float* Wpi2 = (const float*)d_in[9];
    const float* Wpj1 = (const float*)d_in[10];
    const float* Wpj2 = (const float*)d_in[11];
    const float* Wrbf = (const float*)d_in[12];

    node_kernel<<<N_ATOMS, 384>>>(xs, xsph, coord,
                                  Wsi1, Wsi2, Wsj1, Wsj2,
                                  Wpi1, Wpi2, Wpj1, Wpj2);

    dim3 grid((N_ATOMS + TB - 1) / TB, N_ATOMS / TA);
    edge_kernel<<<grid, TB>>>(Wrbf, (float*)d_out);
}